// round 8
// baseline (speedup 1.0000x reference)
#include <cuda_runtime.h>
#include <cuda_fp16.h>
#include <cstdint>

#define EPSILON_F 1e-9f
#define NQ 100
#define L_SEQ 512

#define SLOTS 7
#define CONS_WARPS 14
#define ROWS_PER_ITER 14          // CONS_WARPS rows per pipeline iteration
#define SLOT_BYTES 4096           // 2 rows x 2KB
#define THREADS 480               // 14 consumer warps + 1 producer warp

// fp16 copy of eta, produced once per launch by convert_kernel
__device__ __align__(16) __half g_eta_h[131072];

__device__ __forceinline__ uint32_t smem_u32(const void* p) {
    uint32_t a;
    asm("{ .reg .u64 t; cvta.to.shared.u64 t, %1; cvt.u32.u64 %0, t; }"
        : "=r"(a) : "l"(p));
    return a;
}
__device__ __forceinline__ void mbar_init(uint32_t m, uint32_t cnt) {
    asm volatile("mbarrier.init.shared.b64 [%0], %1;" :: "r"(m), "r"(cnt) : "memory");
}
__device__ __forceinline__ void mbar_expect_tx(uint32_t m, uint32_t bytes) {
    asm volatile("mbarrier.arrive.expect_tx.shared.b64 _, [%0], %1;"
                 :: "r"(m), "r"(bytes) : "memory");
}
__device__ __forceinline__ void mbar_arrive(uint32_t m) {
    asm volatile("mbarrier.arrive.shared.b64 _, [%0];" :: "r"(m) : "memory");
}
__device__ __forceinline__ void mbar_wait(uint32_t m, uint32_t parity) {
    asm volatile(
        "{\n\t.reg .pred P;\n\t"
        "LW_%=:\n\t"
        "mbarrier.try_wait.parity.acquire.cta.shared::cta.b64 P, [%0], %1, 0x989680;\n\t"
        "@P bra LD_%=;\n\t"
        "bra LW_%=;\n\t"
        "LD_%=:\n\t}"
        :: "r"(m), "r"(parity) : "memory");
}
__device__ __forceinline__ void bulk_g2s(uint32_t dst, const void* src,
                                         uint32_t bytes, uint32_t mbar) {
    asm volatile(
        "cp.async.bulk.shared::cluster.global.mbarrier::complete_tx::bytes "
        "[%0], [%1], %2, [%3];"
        :: "r"(dst), "l"(src), "r"(bytes), "r"(mbar) : "memory");
}

__global__ void convert_kernel(const float* __restrict__ eta, int V) {
    const int n2 = V >> 1;
    const float2* e2 = reinterpret_cast<const float2*>(eta);
    __half2* d2 = reinterpret_cast<__half2*>(g_eta_h);
    for (int i = blockIdx.x * blockDim.x + threadIdx.x; i < n2;
         i += gridDim.x * blockDim.x) {
        float2 v = __ldg(e2 + i);
        d2[i] = __floats2half2_rn(v.x, v.y);
    }
    if (blockIdx.x == 0 && threadIdx.x == 0 && (V & 1))
        g_eta_h[V - 1] = __float2half_rn(__ldg(eta + V - 1));
}

// Persistent: 1 CTA/SM. fp16 table lands in smem via one cp.async.bulk.
// Producer thread streams index rows into a 7-slot smem ring (mbarrier
// pipeline); 14 consumer warps gather via the smem crossbar.
__global__ __launch_bounds__(THREADS, 1)
void gather_kernel(const int* __restrict__ idx,
                   const float* __restrict__ t_ptr,
                   float* __restrict__ out, int B, int V) {
    extern __shared__ __align__(16) unsigned char smem[];

    const uint32_t TBL = (uint32_t)((2 * V + 15) & ~15);
    __half* tbl = reinterpret_cast<__half*>(smem);
    float*  ws  = reinterpret_cast<float*>(smem + TBL);
    const uint32_t ring_off = TBL + 64 + 128;

    const uint32_t sbase   = smem_u32(smem);
    const uint32_t m_tbl   = sbase + TBL + 64;
    const uint32_t m_full  = m_tbl + 8;          // 7 x 8B
    const uint32_t m_empty = m_full + 8 * SLOTS; // 7 x 8B
    const uint32_t s_ring  = sbase + ring_off;

    const int tid  = threadIdx.x;
    const int warp = tid >> 5;
    const int lane = tid & 31;

    const float t = __ldg(t_ptr);

    if (tid == 0) {
        mbar_init(m_tbl, 1);
        #pragma unroll
        for (int s = 0; s < SLOTS; s++) {
            mbar_init(m_full + 8 * s, 1);
            mbar_init(m_empty + 8 * s, 2);
        }
    }

    // scalar part: trapz(exp(-E), E) over NQ points (warps 0-3)
    if (tid < 128) {
        float val = 0.0f;
        if (tid < NQ - 1) {
            float Ei = ((float)tid       * (1.0f / (NQ - 1))) * t;
            float Ej = ((float)(tid + 1) * (1.0f / (NQ - 1))) * t;
            val = 0.5f * (__expf(-Ei) + __expf(-Ej)) * (Ej - Ei);
        }
        #pragma unroll
        for (int off = 16; off; off >>= 1)
            val += __shfl_xor_sync(0xffffffffu, val, off);
        if (lane == 0) ws[warp] = val;
    }
    __syncthreads();

    // kick the table copy (200KB, one bulk op)
    if (tid == 0) {
        mbar_expect_tx(m_tbl, TBL);
        bulk_g2s(sbase, g_eta_h, TBL, m_tbl);
    }

    const float base = (ws[0] + ws[1] + ws[2] + ws[3])
                     - 0.5f * t * logf(t + EPSILON_F);

    const int rows_per_cta = (B + gridDim.x - 1) / gridDim.x;
    const int n_iters = (rows_per_cta + ROWS_PER_ITER - 1) / ROWS_PER_ITER;
    const int base_row = blockIdx.x * rows_per_cta;

    if (warp == CONS_WARPS) {
        // ---- producer (lane 0): stream 2-row tiles into the ring ----
        if (lane == 0) {
            uint32_t pphase = 1;                      // first empty-wait passes
            for (int i = 0; i < n_iters; i++) {
                #pragma unroll
                for (int s = 0; s < SLOTS; s++) {
                    mbar_wait(m_empty + 8 * s, pphase);
                    long r0 = (long)base_row + (long)i * ROWS_PER_ITER + 2 * s;
                    if (r0 > (long)B - 2) r0 = (long)B - 2;
                    if (r0 < 0) r0 = 0;
                    mbar_expect_tx(m_full + 8 * s, SLOT_BYTES);
                    bulk_g2s(s_ring + s * SLOT_BYTES,
                             idx + r0 * L_SEQ, SLOT_BYTES, m_full + 8 * s);
                }
                pphase ^= 1;
            }
        }
        return;
    }

    // ---- consumers: warp w owns slot w/2, row (w&1) within the slot ----
    mbar_wait(m_tbl, 0);                              // table ready

    const int slot = warp >> 1;
    const int rin  = warp & 1;
    const int4* pslot = reinterpret_cast<const int4*>(
        smem + ring_off + slot * SLOT_BYTES + rin * 2048);
    const uint32_t mf = m_full  + 8 * slot;
    const uint32_t me = m_empty + 8 * slot;

    uint32_t phase = 0;
    for (int i = 0; i < n_iters; i++) {
        mbar_wait(mf, phase);

        int4 u[4];
        #pragma unroll
        for (int j = 0; j < 4; j++) u[j] = pslot[j * 32 + lane];

        float a = 0.0f, b = 0.0f;
        #pragma unroll
        for (int j = 0; j < 4; j++) {
            a += __half2float(tbl[u[j].x]);
            b += __half2float(tbl[u[j].y]);
            a += __half2float(tbl[u[j].z]);
            b += __half2float(tbl[u[j].w]);
        }
        if (lane == 0) mbar_arrive(me);               // slot reusable

        float s = a + b;
        #pragma unroll
        for (int off = 16; off; off >>= 1)
            s += __shfl_xor_sync(0xffffffffu, s, off);

        const int local = i * ROWS_PER_ITER + warp;
        const int row = base_row + local;
        if (lane == 0 && local < rows_per_cta && row < B)
            out[row] = s + base;

        phase ^= 1;
    }
}

extern "C" void kernel_launch(void* const* d_in, const int* in_sizes, int n_in,
                              void* d_out, int out_size) {
    const int*   idx = (const int*)d_in[0];     // [B, 512] int32
    const float* eta = (const float*)d_in[1];   // [V] f32
    const float* t   = (const float*)d_in[2];   // scalar f32
    float* out = (float*)d_out;

    const int B = in_sizes[0] / L_SEQ;
    const int V = in_sizes[1];

    convert_kernel<<<128, 256>>>(eta, V);

    int dev = 0, sms = 148;
    cudaGetDevice(&dev);
    cudaDeviceGetAttribute(&sms, cudaDevAttrMultiProcessorCount, dev);

    const size_t TBL = (size_t)((2 * V + 15) & ~15);
    const size_t smem = TBL + 64 + 128 + (size_t)SLOTS * SLOT_BYTES;
    cudaFuncSetAttribute(gather_kernel,
                         cudaFuncAttributeMaxDynamicSharedMemorySize, (int)smem);

    gather_kernel<<<sms, THREADS, smem>>>(idx, t, out, B, V);
}

// round 9
// speedup vs baseline: 1.1846x; 1.1846x over previous
#include <cuda_runtime.h>
#include <cuda_fp16.h>
#include <cstdint>

#define EPSILON_F 1e-9f
#define NQ 100
#define L_SEQ 512
#define THREADS 768               // 24 warps; reg ceiling 84/thr

// fp16 copy of eta, produced once per launch by convert_kernel
__device__ __align__(16) __half g_eta_h[131072];

__device__ __forceinline__ uint32_t smem_u32(const void* p) {
    uint32_t a;
    asm("{ .reg .u64 t; cvta.to.shared.u64 t, %1; cvt.u32.u64 %0, t; }"
        : "=r"(a) : "l"(p));
    return a;
}
__device__ __forceinline__ void mbar_init(uint32_t m, uint32_t cnt) {
    asm volatile("mbarrier.init.shared.b64 [%0], %1;" :: "r"(m), "r"(cnt) : "memory");
}
__device__ __forceinline__ void mbar_expect_tx(uint32_t m, uint32_t bytes) {
    asm volatile("mbarrier.arrive.expect_tx.shared.b64 _, [%0], %1;"
                 :: "r"(m), "r"(bytes) : "memory");
}
__device__ __forceinline__ void mbar_wait(uint32_t m, uint32_t parity) {
    asm volatile(
        "{\n\t.reg .pred P;\n\t"
        "LW_%=:\n\t"
        "mbarrier.try_wait.parity.acquire.cta.shared::cta.b64 P, [%0], %1, 0x989680;\n\t"
        "@P bra LD_%=;\n\t"
        "bra LW_%=;\n\t"
        "LD_%=:\n\t}"
        :: "r"(m), "r"(parity) : "memory");
}
__device__ __forceinline__ void bulk_g2s(uint32_t dst, const void* src,
                                         uint32_t bytes, uint32_t mbar) {
    asm volatile(
        "cp.async.bulk.shared::cluster.global.mbarrier::complete_tx::bytes "
        "[%0], [%1], %2, [%3];"
        :: "r"(dst), "l"(src), "r"(bytes), "r"(mbar) : "memory");
}

__global__ void convert_kernel(const float* __restrict__ eta, int V) {
    const int n2 = V >> 1;
    const float2* e2 = reinterpret_cast<const float2*>(eta);
    __half2* d2 = reinterpret_cast<__half2*>(g_eta_h);
    for (int i = blockIdx.x * blockDim.x + threadIdx.x; i < n2;
         i += gridDim.x * blockDim.x) {
        float2 v = __ldg(e2 + i);
        d2[i] = __floats2half2_rn(v.x, v.y);
    }
    if (blockIdx.x == 0 && threadIdx.x == 0 && (V & 1))
        g_eta_h[V - 1] = __float2half_rn(__ldg(eta + V - 1));
}

// Persistent: 1 CTA/SM, 24 warps. fp16 table arrives in smem via ONE
// cp.async.bulk (no staging loop). Depth-3 register ring of index buffers:
// 24 warps x 3 rows x 512B = 36KB/SM of LDG in flight.
__global__ __launch_bounds__(THREADS, 1)
void gather_kernel(const int* __restrict__ idx,
                   const float* __restrict__ t_ptr,
                   float* __restrict__ out, int B, int V) {
    extern __shared__ __align__(16) unsigned char smem[];

    const uint32_t TBL = (uint32_t)((2 * V + 15) & ~15);
    __half* tbl = reinterpret_cast<__half*>(smem);
    float*  ws  = reinterpret_cast<float*>(smem + TBL);

    const uint32_t sbase = smem_u32(smem);
    const uint32_t m_tbl = sbase + TBL + 64;

    const int tid    = threadIdx.x;
    const int warp   = tid >> 5;
    const int lane   = tid & 31;
    const int warps  = blockDim.x >> 5;           // 24
    const int stride = gridDim.x * warps;

    const float t = __ldg(t_ptr);

    if (tid == 0) mbar_init(m_tbl, 1);

    // ---- prologue: issue 3 rows' index loads EARLY ----
    const int row0 = blockIdx.x * warps + warp;
    int4 buf0[4], buf1[4], buf2[4];
    {
        const int r1 = row0 + stride, r2 = row0 + 2 * stride;
        if (row0 < B) {
            const int4* p = reinterpret_cast<const int4*>(idx + (size_t)row0 * L_SEQ);
            #pragma unroll
            for (int j = 0; j < 4; j++) buf0[j] = __ldcs(&p[j * 32 + lane]);
        }
        if (r1 < B) {
            const int4* p = reinterpret_cast<const int4*>(idx + (size_t)r1 * L_SEQ);
            #pragma unroll
            for (int j = 0; j < 4; j++) buf1[j] = __ldcs(&p[j * 32 + lane]);
        }
        if (r2 < B) {
            const int4* p = reinterpret_cast<const int4*>(idx + (size_t)r2 * L_SEQ);
            #pragma unroll
            for (int j = 0; j < 4; j++) buf2[j] = __ldcs(&p[j * 32 + lane]);
        }
    }

    // ---- scalar part: trapz(exp(-E),E), warps 0-3 ----
    if (tid < 128) {
        float val = 0.0f;
        if (tid < NQ - 1) {
            float Ei = ((float)tid       * (1.0f / (NQ - 1))) * t;
            float Ej = ((float)(tid + 1) * (1.0f / (NQ - 1))) * t;
            val = 0.5f * (__expf(-Ei) + __expf(-Ej)) * (Ej - Ei);
        }
        #pragma unroll
        for (int off = 16; off; off >>= 1)
            val += __shfl_xor_sync(0xffffffffu, val, off);
        if (lane == 0) ws[warp] = val;
    }
    __syncthreads();                               // mbar init + ws visible

    // ---- one bulk copy brings the whole fp16 table into smem ----
    if (tid == 0) {
        mbar_expect_tx(m_tbl, TBL);
        bulk_g2s(sbase, g_eta_h, TBL, m_tbl);
    }

    const float base = (ws[0] + ws[1] + ws[2] + ws[3])
                     - 0.5f * t * logf(t + EPSILON_F);

    mbar_wait(m_tbl, 0);                           // table ready

    if (row0 >= B) return;
    int row = row0;

    // one pipeline stage: gather BUF's row, refill BUF from row+3*stride
    #define STAGE(BUF)                                                        \
    {                                                                         \
        float a = 0.0f, b = 0.0f;                                             \
        _Pragma("unroll")                                                     \
        for (int j = 0; j < 4; j++) {                                         \
            a += __half2float(tbl[BUF[j].x]);                                 \
            b += __half2float(tbl[BUF[j].y]);                                 \
            a += __half2float(tbl[BUF[j].z]);                                 \
            b += __half2float(tbl[BUF[j].w]);                                 \
        }                                                                     \
        const int pre = row + 3 * stride;                                     \
        if (pre < B) {                                                        \
            const int4* p = reinterpret_cast<const int4*>(                    \
                idx + (size_t)pre * L_SEQ);                                   \
            _Pragma("unroll")                                                 \
            for (int j = 0; j < 4; j++) BUF[j] = __ldcs(&p[j * 32 + lane]);   \
        }                                                                     \
        float s = a + b;                                                      \
        _Pragma("unroll")                                                     \
        for (int off = 16; off; off >>= 1)                                    \
            s += __shfl_xor_sync(0xffffffffu, s, off);                        \
        if (lane == 0) out[row] = s + base;                                   \
    }

    for (;;) {
        STAGE(buf0); row += stride; if (row >= B) break;
        STAGE(buf1); row += stride; if (row >= B) break;
        STAGE(buf2); row += stride; if (row >= B) break;
    }
    #undef STAGE
}

extern "C" void kernel_launch(void* const* d_in, const int* in_sizes, int n_in,
                              void* d_out, int out_size) {
    const int*   idx = (const int*)d_in[0];     // [B, 512] int32
    const float* eta = (const float*)d_in[1];   // [V] f32
    const float* t   = (const float*)d_in[2];   // scalar f32
    float* out = (float*)d_out;

    const int B = in_sizes[0] / L_SEQ;
    const int V = in_sizes[1];

    convert_kernel<<<128, 256>>>(eta, V);

    int dev = 0, sms = 148;
    cudaGetDevice(&dev);
    cudaDeviceGetAttribute(&sms, cudaDevAttrMultiProcessorCount, dev);

    const size_t TBL = (size_t)((2 * V + 15) & ~15);
    const size_t smem = TBL + 64 + 64;           // table + ws + mbar
    cudaFuncSetAttribute(gather_kernel,
                         cudaFuncAttributeMaxDynamicSharedMemorySize, (int)smem);

    gather_kernel<<<sms, THREADS, smem>>>(idx, t, out, B, V);
}